// round 1
// baseline (speedup 1.0000x reference)
#include <cuda_runtime.h>

// Problem constants (fixed shapes from the reference)
constexpr int B_  = 2;
constexpr int S_  = 2048;
constexpr int D_  = 1024;
constexpr int H_  = 16;
constexpr int DK_ = 64;
constexpr int M_  = B_ * S_;   // 4096 rows for projection GEMMs

// Scratch (device globals -- no allocation allowed in kernel_launch)
__device__ float g_q[(size_t)B_ * S_ * D_];
__device__ float g_k[(size_t)B_ * S_ * D_];
__device__ float g_v[(size_t)B_ * S_ * D_];
__device__ float g_x[(size_t)B_ * S_ * D_];
__device__ float g_att[(size_t)B_ * H_ * S_ * S_];   // 512 MB

// ----------------------------------------------------------------------------
// C[M,N] = A[M,K] @ W[N,K]^T   (both row-major; nn.Linear convention)
// 128x128 block tile, BK=8, 8x8 per thread, 256 threads.
// ----------------------------------------------------------------------------
__global__ __launch_bounds__(256) void sgemm_nt128(
    const float* __restrict__ A, const float* __restrict__ W,
    float* __restrict__ C, int M, int N, int K)
{
    __shared__ float As[8][128];
    __shared__ float Bs[8][128];
    const int bm = blockIdx.y * 128;
    const int bn = blockIdx.x * 128;
    const int tid = threadIdx.x;

    const int lrow = tid >> 1;          // 0..127
    const int lc4  = (tid & 1) * 4;     // 0 or 4
    const int tr   = (tid >> 4) * 8;    // 0..120
    const int tc   = (tid & 15) * 8;    // 0..120

    const float* Aptr = A + (size_t)(bm + lrow) * K + lc4;
    const float* Wptr = W + (size_t)(bn + lrow) * K + lc4;

    float acc[8][8];
#pragma unroll
    for (int i = 0; i < 8; i++)
#pragma unroll
        for (int j = 0; j < 8; j++) acc[i][j] = 0.0f;

    for (int k0 = 0; k0 < K; k0 += 8) {
        float4 a4 = *(const float4*)(Aptr + k0);
        float4 b4 = *(const float4*)(Wptr + k0);
        As[lc4 + 0][lrow] = a4.x; As[lc4 + 1][lrow] = a4.y;
        As[lc4 + 2][lrow] = a4.z; As[lc4 + 3][lrow] = a4.w;
        Bs[lc4 + 0][lrow] = b4.x; Bs[lc4 + 1][lrow] = b4.y;
        Bs[lc4 + 2][lrow] = b4.z; Bs[lc4 + 3][lrow] = b4.w;
        __syncthreads();
#pragma unroll
        for (int kk = 0; kk < 8; kk++) {
            float4 a0 = *(const float4*)&As[kk][tr];
            float4 a1 = *(const float4*)&As[kk][tr + 4];
            float4 b0 = *(const float4*)&Bs[kk][tc];
            float4 b1 = *(const float4*)&Bs[kk][tc + 4];
            float ar[8] = {a0.x, a0.y, a0.z, a0.w, a1.x, a1.y, a1.z, a1.w};
            float br[8] = {b0.x, b0.y, b0.z, b0.w, b1.x, b1.y, b1.z, b1.w};
#pragma unroll
            for (int i = 0; i < 8; i++)
#pragma unroll
                for (int j = 0; j < 8; j++)
                    acc[i][j] = fmaf(ar[i], br[j], acc[i][j]);
        }
        __syncthreads();
    }

#pragma unroll
    for (int i = 0; i < 8; i++) {
        float* cp = C + (size_t)(bm + tr + i) * N + bn + tc;
        *(float4*)cp       = make_float4(acc[i][0], acc[i][1], acc[i][2], acc[i][3]);
        *(float4*)(cp + 4) = make_float4(acc[i][4], acc[i][5], acc[i][6], acc[i][7]);
    }
}

// ----------------------------------------------------------------------------
// scores[b,h,q,k] = (1/8) * sum_d Q[b,q,h*64+d] * K[b,k,h*64+d]
// One block = (b,h, 64 q, 64 k). Whole DK=64 in smem (transposed, padded).
// ----------------------------------------------------------------------------
__global__ __launch_bounds__(256) void scores_kernel(
    const float* __restrict__ Q, const float* __restrict__ Kp,
    float* __restrict__ att)
{
    __shared__ float Qs[64][68];   // [dk][q]
    __shared__ float Ks[64][68];   // [dk][k]
    const int bh = blockIdx.z;
    const int b = bh >> 4, h = bh & 15;
    const int q0 = blockIdx.y * 64;
    const int k0 = blockIdx.x * 64;
    const int tid = threadIdx.x;

    const float* Qb = Q  + (size_t)b * S_ * D_ + (size_t)h * DK_;
    const float* Kb = Kp + (size_t)b * S_ * D_ + (size_t)h * DK_;

#pragma unroll
    for (int i = 0; i < 4; i++) {
        int idx = tid + i * 256;        // float4 index over 64x64 tile
        int row = idx >> 4;             // 16 float4 per row
        int c4  = (idx & 15) * 4;
        float4 qv = *(const float4*)(Qb + (size_t)(q0 + row) * D_ + c4);
        float4 kv = *(const float4*)(Kb + (size_t)(k0 + row) * D_ + c4);
        Qs[c4 + 0][row] = qv.x; Qs[c4 + 1][row] = qv.y;
        Qs[c4 + 2][row] = qv.z; Qs[c4 + 3][row] = qv.w;
        Ks[c4 + 0][row] = kv.x; Ks[c4 + 1][row] = kv.y;
        Ks[c4 + 2][row] = kv.z; Ks[c4 + 3][row] = kv.w;
    }
    __syncthreads();

    const int tr = (tid >> 4) * 4;
    const int tc = (tid & 15) * 4;
    float acc[4][4];
#pragma unroll
    for (int i = 0; i < 4; i++)
#pragma unroll
        for (int j = 0; j < 4; j++) acc[i][j] = 0.0f;

#pragma unroll
    for (int kk = 0; kk < 64; kk++) {
        float4 a4 = *(const float4*)&Qs[kk][tr];
        float4 b4 = *(const float4*)&Ks[kk][tc];
        float ar[4] = {a4.x, a4.y, a4.z, a4.w};
        float br[4] = {b4.x, b4.y, b4.z, b4.w};
#pragma unroll
        for (int i = 0; i < 4; i++)
#pragma unroll
            for (int j = 0; j < 4; j++)
                acc[i][j] = fmaf(ar[i], br[j], acc[i][j]);
    }

    const float scale = 0.125f;   // 1/sqrt(64)
#pragma unroll
    for (int i = 0; i < 4; i++) {
        float* op = att + (size_t)bh * S_ * S_ + (size_t)(q0 + tr + i) * S_ + k0 + tc;
        *(float4*)op = make_float4(acc[i][0] * scale, acc[i][1] * scale,
                                   acc[i][2] * scale, acc[i][3] * scale);
    }
}

// ----------------------------------------------------------------------------
// softmax over the HEAD axis (faithful to the reference quirk).
// One thread per (b,q,k); loads/stores stride S*S over h (coalesced along k).
// ----------------------------------------------------------------------------
__global__ __launch_bounds__(256) void softmax_h_kernel(float* __restrict__ att)
{
    const size_t SS = (size_t)S_ * S_;            // 2^22
    size_t idx = (size_t)blockIdx.x * 256 + threadIdx.x;   // over B*S*S
    size_t b   = idx >> 22;
    size_t rem = idx & (SS - 1);
    size_t base = b * (size_t)H_ * SS + rem;

    float v[H_];
    float m = -1e30f;
#pragma unroll
    for (int h = 0; h < H_; h++) {
        v[h] = att[base + (size_t)h * SS];
        m = fmaxf(m, v[h]);
    }
    float s = 0.0f;
#pragma unroll
    for (int h = 0; h < H_; h++) {
        v[h] = __expf(v[h] - m);
        s += v[h];
    }
    float inv = 1.0f / s;
#pragma unroll
    for (int h = 0; h < H_; h++)
        att[base + (size_t)h * SS] = v[h] * inv;
}

// ----------------------------------------------------------------------------
// x[b,q,h*64+d] = sum_k attn[b,h,q,k] * V[b,k,h*64+d]
// One block = (b,h, 64 q, all 64 d). K-loop over S in tiles of 32.
// ----------------------------------------------------------------------------
__global__ __launch_bounds__(256) void attnv_kernel(
    const float* __restrict__ att, const float* __restrict__ V,
    float* __restrict__ X)
{
    __shared__ float As[32][68];   // [k][q]
    __shared__ float Bs[32][68];   // [k][d]
    const int bh = blockIdx.y;
    const int b = bh >> 4, h = bh & 15;
    const int q0 = blockIdx.x * 64;
    const int tid = threadIdx.x;

    const float* Ab = att + (size_t)bh * S_ * S_;
    const float* Vb = V + (size_t)b * S_ * D_ + (size_t)h * DK_;

    const int tr = (tid >> 4) * 4;
    const int tc = (tid & 15) * 4;
    float acc[4][4];
#pragma unroll
    for (int i = 0; i < 4; i++)
#pragma unroll
        for (int j = 0; j < 4; j++) acc[i][j] = 0.0f;

    for (int k0 = 0; k0 < S_; k0 += 32) {
#pragma unroll
        for (int i = 0; i < 2; i++) {
            int idx = tid + i * 256;
            // attn tile: 64 q x 32 k (8 float4 per row), transpose into As[k][q]
            int arow = idx >> 3;
            int ac4  = (idx & 7) * 4;
            float4 a4 = *(const float4*)(Ab + (size_t)(q0 + arow) * S_ + k0 + ac4);
            As[ac4 + 0][arow] = a4.x; As[ac4 + 1][arow] = a4.y;
            As[ac4 + 2][arow] = a4.z; As[ac4 + 3][arow] = a4.w;
            // V tile: 32 k x 64 d (16 float4 per row), direct into Bs[k][d]
            int brow = idx >> 4;
            int bc4  = (idx & 15) * 4;
            float4 b4 = *(const float4*)(Vb + (size_t)(k0 + brow) * D_ + bc4);
            *(float4*)&Bs[brow][bc4] = b4;
        }
        __syncthreads();
#pragma unroll
        for (int kk = 0; kk < 32; kk++) {
            float4 a4 = *(const float4*)&As[kk][tr];
            float4 b4 = *(const float4*)&Bs[kk][tc];
            float ar[4] = {a4.x, a4.y, a4.z, a4.w};
            float br[4] = {b4.x, b4.y, b4.z, b4.w};
#pragma unroll
            for (int i = 0; i < 4; i++)
#pragma unroll
                for (int j = 0; j < 4; j++)
                    acc[i][j] = fmaf(ar[i], br[j], acc[i][j]);
        }
        __syncthreads();
    }

#pragma unroll
    for (int i = 0; i < 4; i++) {
        float* xp = X + (size_t)((size_t)b * S_ + q0 + tr + i) * D_ + (size_t)h * DK_ + tc;
        *(float4*)xp = make_float4(acc[i][0], acc[i][1], acc[i][2], acc[i][3]);
    }
}

// ----------------------------------------------------------------------------
extern "C" void kernel_launch(void* const* d_in, const int* in_sizes, int n_in,
                              void* d_out, int out_size)
{
    (void)in_sizes; (void)n_in; (void)out_size;
    const float* qi = (const float*)d_in[0];
    const float* ki = (const float*)d_in[1];
    const float* vi = (const float*)d_in[2];
    // d_in[3] is the mask -- reference discards masked_fill, so it is unused.
    const float* Wq = (const float*)d_in[4];
    const float* Wk = (const float*)d_in[5];
    const float* Wv = (const float*)d_in[6];
    const float* Wo = (const float*)d_in[7];
    float* out = (float*)d_out;

    float *gq, *gk, *gv, *gx, *gatt;
    cudaGetSymbolAddress((void**)&gq,   g_q);
    cudaGetSymbolAddress((void**)&gk,   g_k);
    cudaGetSymbolAddress((void**)&gv,   g_v);
    cudaGetSymbolAddress((void**)&gx,   g_x);
    cudaGetSymbolAddress((void**)&gatt, g_att);

    dim3 gproj(D_ / 128, M_ / 128);          // (8, 32)
    sgemm_nt128<<<gproj, 256>>>(qi, Wq, gq, M_, D_, D_);
    sgemm_nt128<<<gproj, 256>>>(ki, Wk, gk, M_, D_, D_);
    sgemm_nt128<<<gproj, 256>>>(vi, Wv, gv, M_, D_, D_);

    dim3 gsc(S_ / 64, S_ / 64, B_ * H_);     // (32, 32, 32)
    scores_kernel<<<gsc, 256>>>(gq, gk, gatt);

    int smx_blocks = (int)(((size_t)B_ * S_ * S_) / 256);   // 32768
    softmax_h_kernel<<<smx_blocks, 256>>>(gatt);

    dim3 gav(S_ / 64, B_ * H_);              // (32, 32)
    attnv_kernel<<<gav, 256>>>(gatt, gv, gx);

    sgemm_nt128<<<gproj, 256>>>(gx, Wo, out, M_, D_, D_);
}

// round 3
// speedup vs baseline: 2.1369x; 2.1369x over previous
#include <cuda_runtime.h>
#include <cuda_bf16.h>
#include <cstdint>

// Problem constants (fixed shapes)
constexpr int B_  = 2;
constexpr int S_  = 2048;
constexpr int D_  = 1024;
constexpr int H_  = 16;
constexpr int M_  = B_ * S_;            // 4096
constexpr size_t SS_ = (size_t)S_ * S_; // 4M

// ---------------------------------------------------------------------------
// Device-global scratch
// ---------------------------------------------------------------------------
__device__ float g_q[(size_t)M_ * D_];
__device__ float g_k[(size_t)M_ * D_];
__device__ float g_v[(size_t)M_ * D_];
__device__ float g_x[(size_t)M_ * D_];
__device__ float g_att[(size_t)B_ * H_ * SS_];            // 512 MB fp32 scores

__device__ __nv_bfloat16 g_att_hi[(size_t)B_ * H_ * SS_]; // 256 MB
__device__ __nv_bfloat16 g_att_lo[(size_t)B_ * H_ * SS_];

__device__ __nv_bfloat16 g_qi_hi[(size_t)M_ * D_], g_qi_lo[(size_t)M_ * D_];
__device__ __nv_bfloat16 g_ki_hi[(size_t)M_ * D_], g_ki_lo[(size_t)M_ * D_];
__device__ __nv_bfloat16 g_vi_hi[(size_t)M_ * D_], g_vi_lo[(size_t)M_ * D_];
__device__ __nv_bfloat16 g_q_hi [(size_t)M_ * D_], g_q_lo [(size_t)M_ * D_];
__device__ __nv_bfloat16 g_k_hi [(size_t)M_ * D_], g_k_lo [(size_t)M_ * D_];
__device__ __nv_bfloat16 g_x_hi [(size_t)M_ * D_], g_x_lo [(size_t)M_ * D_];
__device__ __nv_bfloat16 g_vt_hi[(size_t)B_ * H_ * 64 * S_];  // [bh][64][2048]
__device__ __nv_bfloat16 g_vt_lo[(size_t)B_ * H_ * 64 * S_];
__device__ __nv_bfloat16 g_wq_hi[(size_t)D_ * D_], g_wq_lo[(size_t)D_ * D_];
__device__ __nv_bfloat16 g_wk_hi[(size_t)D_ * D_], g_wk_lo[(size_t)D_ * D_];
__device__ __nv_bfloat16 g_wv_hi[(size_t)D_ * D_], g_wv_lo[(size_t)D_ * D_];
__device__ __nv_bfloat16 g_wo_hi[(size_t)D_ * D_], g_wo_lo[(size_t)D_ * D_];

// ---------------------------------------------------------------------------
// PTX helpers (compute_103-baseline safe: mma.sync / ldmatrix / cp.async)
// ---------------------------------------------------------------------------
__device__ __forceinline__ uint32_t smem_u32(const void* p) {
    uint32_t a;
    asm("{ .reg .u64 t; cvta.to.shared.u64 t, %1; cvt.u32.u64 %0, t; }"
        : "=r"(a) : "l"(p));
    return a;
}
__device__ __forceinline__ void cp16(uint32_t dst, const void* src) {
    asm volatile("cp.async.cg.shared.global [%0], [%1], 16;"
                 :: "r"(dst), "l"(src));
}
#define CP_COMMIT() asm volatile("cp.async.commit_group;" ::: "memory")
#define CP_WAIT(n)  asm volatile("cp.async.wait_group %0;" :: "n"(n) : "memory")

#define LDSM_X4(r, addr)                                                       \
    asm volatile("ldmatrix.sync.aligned.m8n8.x4.shared.b16 {%0,%1,%2,%3},[%4];"\
                 : "=r"((r)[0]), "=r"((r)[1]), "=r"((r)[2]), "=r"((r)[3])      \
                 : "r"(addr))
#define LDSM_X2(r, addr)                                                       \
    asm volatile("ldmatrix.sync.aligned.m8n8.x2.shared.b16 {%0,%1},[%2];"      \
                 : "=r"((r)[0]), "=r"((r)[1]) : "r"(addr))
#define MMA16816(c, a, b)                                                      \
    asm volatile("mma.sync.aligned.m16n8k16.row.col.f32.bf16.bf16.f32 "        \
                 "{%0,%1,%2,%3},{%4,%5,%6,%7},{%8,%9},{%0,%1,%2,%3};"          \
                 : "+f"((c)[0]), "+f"((c)[1]), "+f"((c)[2]), "+f"((c)[3])      \
                 : "r"((a)[0]), "r"((a)[1]), "r"((a)[2]), "r"((a)[3]),         \
                   "r"((b)[0]), "r"((b)[1]))

// ---------------------------------------------------------------------------
// fp32 -> (bf16 hi, bf16 lo) split, vectorized
// ---------------------------------------------------------------------------
__global__ __launch_bounds__(256) void split_bf16_kernel(
    const float4* __restrict__ x, __nv_bfloat162* __restrict__ hi,
    __nv_bfloat162* __restrict__ lo, int n4)
{
    int i = blockIdx.x * 256 + threadIdx.x;
    if (i >= n4) return;
    float4 v = x[i];
    __nv_bfloat16 hx = __float2bfloat16(v.x);
    __nv_bfloat16 hy = __float2bfloat16(v.y);
    __nv_bfloat16 hz = __float2bfloat16(v.z);
    __nv_bfloat16 hw = __float2bfloat16(v.w);
    __nv_bfloat16 lx = __float2bfloat16(v.x - __bfloat162float(hx));
    __nv_bfloat16 ly = __float2bfloat16(v.y - __bfloat162float(hy));
    __nv_bfloat16 lz = __float2bfloat16(v.z - __bfloat162float(hz));
    __nv_bfloat16 lw = __float2bfloat16(v.w - __bfloat162float(hw));
    hi[2 * i]     = __nv_bfloat162(hx, hy);
    hi[2 * i + 1] = __nv_bfloat162(hz, hw);
    lo[2 * i]     = __nv_bfloat162(lx, ly);
    lo[2 * i + 1] = __nv_bfloat162(lz, lw);
}

// ---------------------------------------------------------------------------
// V [b, k(2048), d(1024)] fp32  ->  Vt hi/lo [bh, d(64), k(2048)] bf16
// ---------------------------------------------------------------------------
__global__ __launch_bounds__(256) void transpose_split_v(
    const float* __restrict__ V, __nv_bfloat16* __restrict__ hi,
    __nv_bfloat16* __restrict__ lo)
{
    __shared__ float t[32][33];
    const int b  = blockIdx.z;
    const int k0 = blockIdx.y * 32;
    const int d0 = blockIdx.x * 32;
    const int tx = threadIdx.x & 31, ty = threadIdx.x >> 5;  // 32 x 8
#pragma unroll
    for (int i = 0; i < 4; i++) {
        int k = k0 + ty + i * 8;
        t[ty + i * 8][tx] = V[((size_t)b * S_ + k) * D_ + d0 + tx];
    }
    __syncthreads();
#pragma unroll
    for (int i = 0; i < 4; i++) {
        int d = d0 + ty + i * 8;
        int h = d >> 6, dh = d & 63;
        float val = t[tx][ty + i * 8];
        size_t o = ((size_t)(b * H_ + h) * 64 + dh) * S_ + k0 + tx;
        __nv_bfloat16 hv = __float2bfloat16(val);
        hi[o] = hv;
        lo[o] = __float2bfloat16(val - __bfloat162float(hv));
    }
}

// ---------------------------------------------------------------------------
// Generic NT bf16x3 GEMM: C[M,N] (+scale) = (Ahi+Alo)[M,K] @ (Bhi+Blo)[N,K]^T
// BM=128, BK=32 fixed; BN / warp-grid templated. 256 threads, cp.async 2-stage.
// Per-z offsets: off = (z&15)*zs1 + (z>>4)*zs2 (z = blockIdx.z).
// ---------------------------------------------------------------------------
template<int BN, int WGM, int WGN>
__global__ __launch_bounds__(256, 1) void gemm_bf16x3_mma(
    const __nv_bfloat16* __restrict__ Ahi, const __nv_bfloat16* __restrict__ Alo,
    const __nv_bfloat16* __restrict__ Bhi, const __nv_bfloat16* __restrict__ Blo,
    float* __restrict__ C, int K, int lda, int ldb, int ldc,
    size_t zsA1, size_t zsA2, size_t zsB1, size_t zsB2,
    size_t zsC1, size_t zsC2, float scale)
{
    constexpr int BM  = 128, BK = 32;
    constexpr int WTM = BM / WGM;           // warp tile M
    constexpr int WTN = BN / WGN;           // warp tile N
    constexpr int MT  = WTM / 16;
    constexpr int NT  = WTN / 8;
    constexpr int LDSR = BK + 8;            // 40 bf16 row stride (80 B)
    constexpr int A_BYTES = BM * LDSR * 2;  // one component
    constexpr int B_BYTES = BN * LDSR * 2;
    constexpr int STAGE   = 2 * A_BYTES + 2 * B_BYTES;
    constexpr int CHUNKS  = (2 * BM + 2 * BN) * 4;   // 16B chunks per stage

    extern __shared__ char smem_raw[];
    const uint32_t sbase = smem_u32(smem_raw);

    const int tid  = threadIdx.x;
    const int wid  = tid >> 5, lane = tid & 31;
    const int wm   = wid / WGN, wn = wid % WGN;
    const int bm   = blockIdx.y * BM;
    const int bn   = blockIdx.x * BN;
    const int z    = blockIdx.z;

    const size_t offA = (size_t)(z & 15) * zsA1 + (size_t)(z >> 4) * zsA2;
    const size_t offB = (size_t)(z & 15) * zsB1 + (size_t)(z >> 4) * zsB2;
    const size_t offC = (size_t)(z & 15) * zsC1 + (size_t)(z >> 4) * zsC2;
    const __nv_bfloat16* pAh = Ahi + offA;
    const __nv_bfloat16* pAl = Alo + offA;
    const __nv_bfloat16* pBh = Bhi + offB;
    const __nv_bfloat16* pBl = Blo + offB;
    float* pC = C + offC;

    float acc[MT][NT][4];
#pragma unroll
    for (int i = 0; i < MT; i++)
#pragma unroll
        for (int j = 0; j < NT; j++)
#pragma unroll
            for (int q = 0; q < 4; q++) acc[i][j][q] = 0.0f;

    const int NC = K / BK;

    auto issue = [&](int c) {
        const uint32_t sb = sbase + (uint32_t)(c & 1) * STAGE;
        const int k0 = c * BK;
#pragma unroll
        for (int it = 0; it < CHUNKS / 256; it++) {
            int idx = tid + it * 256;
            int r4 = idx >> 2, kc = idx & 3;
            const __nv_bfloat16* src;
            uint32_t dst;
            if (r4 < BM) {
                src = pAh + (size_t)(bm + r4) * lda + k0 + kc * 8;
                dst = sb + (uint32_t)(r4 * (LDSR * 2) + kc * 16);
            } else if (r4 < 2 * BM) {
                int r = r4 - BM;
                src = pAl + (size_t)(bm + r) * lda + k0 + kc * 8;
                dst = sb + A_BYTES + (uint32_t)(r * (LDSR * 2) + kc * 16);
            } else if (r4 < 2 * BM + BN) {
                int r = r4 - 2 * BM;
                src = pBh + (size_t)(bn + r) * ldb + k0 + kc * 8;
                dst = sb + 2 * A_BYTES + (uint32_t)(r * (LDSR * 2) + kc * 16);
            } else {
                int r = r4 - 2 * BM - BN;
                src = pBl + (size_t)(bn + r) * ldb + k0 + kc * 8;
                dst = sb + 2 * A_BYTES + B_BYTES + (uint32_t)(r * (LDSR * 2) + kc * 16);
            }
            cp16(dst, src);
        }
        CP_COMMIT();
    };

    issue(0);

    for (int c = 0; c < NC; c++) {
        if (c + 1 < NC) { issue(c + 1); CP_WAIT(1); }
        else            { CP_WAIT(0); }
        __syncthreads();

        const uint32_t sA  = sbase + (uint32_t)(c & 1) * STAGE;
        const uint32_t sB  = sA + 2 * A_BYTES;

        // per-lane intra-tile offsets
        const int arow = lane & 15;            // row within 16
        const int acb  = (lane >> 4) * 8;      // 8-col group (bf16)
        const int brow = lane & 7;
        const int bcb  = ((lane >> 3) & 1) * 8;

#pragma unroll
        for (int ks = 0; ks < 2; ks++) {
            uint32_t ahi[MT][4], alo[MT][4], bhi[NT][2], blo[NT][2];
#pragma unroll
            for (int mt = 0; mt < MT; mt++) {
                uint32_t off = (uint32_t)(((wm * WTM + mt * 16 + arow) * LDSR
                                           + ks * 16 + acb) * 2);
                LDSM_X4(ahi[mt], sA + off);
                LDSM_X4(alo[mt], sA + A_BYTES + off);
            }
#pragma unroll
            for (int nt = 0; nt < NT; nt++) {
                uint32_t off = (uint32_t)(((wn * WTN + nt * 8 + brow) * LDSR
                                           + ks * 16 + bcb) * 2);
                LDSM_X2(bhi[nt], sB + off);
                LDSM_X2(blo[nt], sB + B_BYTES + off);
            }
#pragma unroll
            for (int mt = 0; mt < MT; mt++)
#pragma unroll
                for (int nt = 0; nt < NT; nt++) {
                    MMA16816(acc[mt][nt], ahi[mt], bhi[nt]);
                    MMA16816(acc[mt][nt], ahi[mt], blo[nt]);
                    MMA16816(acc[mt][nt], alo[mt], bhi[nt]);
                }
        }
        __syncthreads();
    }

    // Epilogue: scaled fp32 stores (float2 per fragment half)
    const int erow = lane >> 2;
    const int ecol = 2 * (lane & 3);
#pragma unroll
    for (int mt = 0; mt < MT; mt++) {
        const int row = bm + wm * WTM + mt * 16 + erow;
#pragma unroll
        for (int nt = 0; nt < NT; nt++) {
            const int col = bn + wn * WTN + nt * 8 + ecol;
            float2 v0 = make_float2(acc[mt][nt][0] * scale, acc[mt][nt][1] * scale);
            float2 v1 = make_float2(acc[mt][nt][2] * scale, acc[mt][nt][3] * scale);
            *(float2*)(pC + (size_t)row * ldc + col)       = v0;
            *(float2*)(pC + (size_t)(row + 8) * ldc + col) = v1;
        }
    }
}

// ---------------------------------------------------------------------------
// softmax over the HEAD axis; emits attn as bf16 hi/lo
// ---------------------------------------------------------------------------
__global__ __launch_bounds__(256) void softmax_h_split(
    const float* __restrict__ att, __nv_bfloat16* __restrict__ hi,
    __nv_bfloat16* __restrict__ lo)
{
    size_t idx = (size_t)blockIdx.x * 256 + threadIdx.x;   // over B*S*S
    size_t b   = idx >> 22;
    size_t rem = idx & (SS_ - 1);
    size_t base = b * (size_t)H_ * SS_ + rem;

    float v[H_];
    float m = -1e30f;
#pragma unroll
    for (int h = 0; h < H_; h++) {
        v[h] = att[base + (size_t)h * SS_];
        m = fmaxf(m, v[h]);
    }
    float s = 0.0f;
#pragma unroll
    for (int h = 0; h < H_; h++) {
        v[h] = __expf(v[h] - m);
        s += v[h];
    }
    float inv = 1.0f / s;
#pragma unroll
    for (int h = 0; h < H_; h++) {
        float p = v[h] * inv;
        __nv_bfloat16 ph = __float2bfloat16(p);
        size_t o = base + (size_t)h * SS_;
        hi[o] = ph;
        lo[o] = __float2bfloat16(p - __bfloat162float(ph));
    }
}

// ---------------------------------------------------------------------------
extern "C" void kernel_launch(void* const* d_in, const int* in_sizes, int n_in,
                              void* d_out, int out_size)
{
    (void)in_sizes; (void)n_in; (void)out_size;
    const float* qi = (const float*)d_in[0];
    const float* ki = (const float*)d_in[1];
    const float* vi = (const float*)d_in[2];
    // d_in[3] = mask: reference discards masked_fill -> unused
    const float* Wq = (const float*)d_in[4];
    const float* Wk = (const float*)d_in[5];
    const float* Wv = (const float*)d_in[6];
    const float* Wo = (const float*)d_in[7];
    float* out = (float*)d_out;

    float *gq, *gk, *gv, *gx, *gatt;
    cudaGetSymbolAddress((void**)&gq,   g_q);
    cudaGetSymbolAddress((void**)&gk,   g_k);
    cudaGetSymbolAddress((void**)&gv,   g_v);
    cudaGetSymbolAddress((void**)&gx,   g_x);
    cudaGetSymbolAddress((void**)&gatt, g_att);

    __nv_bfloat16 *qih, *qil, *kih, *kil, *vih, *vil;
    __nv_bfloat16 *qh, *ql, *kh, *kl, *xh, *xl, *vth, *vtl, *ath, *atl;
    __nv_bfloat16 *wqh, *wql, *wkh, *wkl, *wvh, *wvl, *woh, *wol;
    cudaGetSymbolAddress((void**)&qih, g_qi_hi); cudaGetSymbolAddress((void**)&qil, g_qi_lo);
    cudaGetSymbolAddress((void**)&kih, g_ki_hi); cudaGetSymbolAddress((void**)&kil, g_ki_lo);
    cudaGetSymbolAddress((void**)&vih, g_vi_hi); cudaGetSymbolAddress((void**)&vil, g_vi_lo);
    cudaGetSymbolAddress((void**)&qh,  g_q_hi);  cudaGetSymbolAddress((void**)&ql,  g_q_lo);
    cudaGetSymbolAddress((void**)&kh,  g_k_hi);  cudaGetSymbolAddress((void**)&kl,  g_k_lo);
    cudaGetSymbolAddress((void**)&xh,  g_x_hi);  cudaGetSymbolAddress((void**)&xl,  g_x_lo);
    cudaGetSymbolAddress((void**)&vth, g_vt_hi); cudaGetSymbolAddress((void**)&vtl, g_vt_lo);
    cudaGetSymbolAddress((void**)&ath, g_att_hi);cudaGetSymbolAddress((void**)&atl, g_att_lo);
    cudaGetSymbolAddress((void**)&wqh, g_wq_hi); cudaGetSymbolAddress((void**)&wql, g_wq_lo);
    cudaGetSymbolAddress((void**)&wkh, g_wk_hi); cudaGetSymbolAddress((void**)&wkl, g_wk_lo);
    cudaGetSymbolAddress((void**)&wvh, g_wv_hi); cudaGetSymbolAddress((void**)&wvl, g_wv_lo);
    cudaGetSymbolAddress((void**)&woh, g_wo_hi); cudaGetSymbolAddress((void**)&wol, g_wo_lo);

    // GEMM variants: big (BN=128) and narrow (BN=64 for attn·V)
    auto* gemm_big  = gemm_bf16x3_mma<128, 2, 4>;
    auto* gemm_nar  = gemm_bf16x3_mma<64, 4, 2>;
    constexpr int SMEM_BIG = 2 * (2 * 128 * 40 * 2 + 2 * 128 * 40 * 2); // 81920
    constexpr int SMEM_NAR = 2 * (2 * 128 * 40 * 2 + 2 * 64 * 40 * 2);  // 61440
    cudaFuncSetAttribute(gemm_big, cudaFuncAttributeMaxDynamicSharedMemorySize, SMEM_BIG);
    cudaFuncSetAttribute(gemm_nar, cudaFuncAttributeMaxDynamicSharedMemorySize, SMEM_NAR);

    const int nInp4 = (M_ * D_) / 4;
    const int nW4   = (D_ * D_) / 4;

    // 1) split inputs + weights to bf16 hi/lo
    split_bf16_kernel<<<nInp4 / 256, 256>>>((const float4*)qi, (__nv_bfloat162*)qih, (__nv_bfloat162*)qil, nInp4);
    split_bf16_kernel<<<nInp4 / 256, 256>>>((const float4*)ki, (__nv_bfloat162*)kih, (__nv_bfloat162*)kil, nInp4);
    split_bf16_kernel<<<nInp4 / 256, 256>>>((const float4*)vi, (__nv_bfloat162*)vih, (__nv_bfloat162*)vil, nInp4);
    split_bf16_kernel<<<nW4 / 256, 256>>>((const float4*)Wq, (__nv_bfloat162*)wqh, (__nv_bfloat162*)wql, nW4);
    split_bf16_kernel<<<nW4 / 256, 256>>>((const float4*)Wk, (__nv_bfloat162*)wkh, (__nv_bfloat162*)wkl, nW4);
    split_bf16_kernel<<<nW4 / 256, 256>>>((const float4*)Wv, (__nv_bfloat162*)wvh, (__nv_bfloat162*)wvl, nW4);
    split_bf16_kernel<<<nW4 / 256, 256>>>((const float4*)Wo, (__nv_bfloat162*)woh, (__nv_bfloat162*)wol, nW4);

    // 2) projections: [4096,1024] = in @ W^T
    dim3 gproj(D_ / 128, M_ / 128, 1);   // (8, 32, 1)
    gemm_big<<<gproj, 256, SMEM_BIG>>>(qih, qil, wqh, wql, gq, D_, D_, D_, D_,
                                       0, 0, 0, 0, 0, 0, 1.0f);
    gemm_big<<<gproj, 256, SMEM_BIG>>>(kih, kil, wkh, wkl, gk, D_, D_, D_, D_,
                                       0, 0, 0, 0, 0, 0, 1.0f);
    gemm_big<<<gproj, 256, SMEM_BIG>>>(vih, vil, wvh, wvl, gv, D_, D_, D_, D_,
                                       0, 0, 0, 0, 0, 0, 1.0f);

    // 3) split q,k; transpose+split v
    split_bf16_kernel<<<nInp4 / 256, 256>>>((const float4*)gq, (__nv_bfloat162*)qh, (__nv_bfloat162*)ql, nInp4);
    split_bf16_kernel<<<nInp4 / 256, 256>>>((const float4*)gk, (__nv_bfloat162*)kh, (__nv_bfloat162*)kl, nInp4);
    dim3 gtr(D_ / 32, S_ / 32, B_);      // (32, 64, 2)
    transpose_split_v<<<gtr, 256>>>(gv, vth, vtl);

    // 4) scores[bh] = (Q_h @ K_h^T) / 8   -- per-z offsets: A,B = b*S*D + h*64
    dim3 gsc(S_ / 128, S_ / 128, B_ * H_);   // (16, 16, 32)
    gemm_big<<<gsc, 256, SMEM_BIG>>>(qh, ql, kh, kl, gatt, 64, D_, D_, S_,
                                     64, (size_t)S_ * D_,
                                     64, (size_t)S_ * D_,
                                     SS_, (size_t)H_ * SS_, 0.125f);

    // 5) softmax over heads -> attn hi/lo bf16
    int smx_blocks = (int)(((size_t)B_ * SS_) / 256);
    softmax_h_split<<<smx_blocks, 256>>>(gatt, ath, atl);

    // 6) x[bh] = attn[bh] @ Vt[bh]^T  (N = 64)
    dim3 gav(1, S_ / 128, B_ * H_);          // (1, 16, 32)
    gemm_nar<<<gav, 256, SMEM_NAR>>>(ath, atl, vth, vtl, gx, S_, S_, S_, D_,
                                     SS_, (size_t)H_ * SS_,
                                     (size_t)64 * S_, (size_t)H_ * 64 * S_,
                                     64, (size_t)S_ * D_, 1.0f);

    // 7) out = x @ Wo^T
    split_bf16_kernel<<<nInp4 / 256, 256>>>((const float4*)gx, (__nv_bfloat162*)xh, (__nv_bfloat162*)xl, nInp4);
    gemm_big<<<gproj, 256, SMEM_BIG>>>(xh, xl, woh, wol, out, D_, D_, D_, D_,
                                       0, 0, 0, 0, 0, 0, 1.0f);
}